// round 1
// baseline (speedup 1.0000x reference)
#include <cuda_runtime.h>
#include <cstdint>

// Problem constants
#define BATCH 4
#define CDIM  256
#define DDIM  32
#define NPIX  4096
#define RTOT  320          // D (q) + D (k) + C (v)
#define LN_EPS 1e-5f
// (1/sqrt(32)) * log2(e): scores computed directly in log2 domain
#define SCALE_LOG2E 0.2550348639f

#define MQ 64              // queries per attention block
#define TK 64              // keys per tile

// Scratch: fused QKV projections, layout [b][n][320] (r contiguous per pixel)
__device__ float g_qkv[(size_t)BATCH * NPIX * RTOT];

__device__ __forceinline__ float ex2f(float v) {
    float y;
    asm("ex2.approx.ftz.f32 %0, %1;" : "=f"(y) : "f"(v));
    return y;
}

// ---------------------------------------------------------------------------
// Kernel 1: QKV projection. Per batch: W_all[320,256] x X[256,4096] + bias.
// Tiling: 64(r) x 64(n) x 16(k), 256 threads, 4x4 microtile.
// ---------------------------------------------------------------------------
__global__ __launch_bounds__(256) void qkv_kernel(
    const float* __restrict__ x,
    const float* __restrict__ wq, const float* __restrict__ bq,
    const float* __restrict__ wk, const float* __restrict__ bk,
    const float* __restrict__ wv, const float* __restrict__ bv)
{
    __shared__ float Ws[16][65];   // [k][r]
    __shared__ float Xs[16][65];   // [k][n]

    const int b  = blockIdx.z;
    const int r0 = blockIdx.x * 64;
    const int n0 = blockIdx.y * 64;
    const int tid = threadIdx.x;
    const int tx = tid & 15, ty = tid >> 4;

    const float* xb = x + (size_t)b * CDIM * NPIX;

    float acc[4][4];
#pragma unroll
    for (int i = 0; i < 4; i++)
#pragma unroll
        for (int j = 0; j < 4; j++) acc[i][j] = 0.0f;

    for (int kk = 0; kk < CDIM; kk += 16) {
        // Load weight tile (select among wq/wk/wv by global row)
#pragma unroll
        for (int l = 0; l < 4; l++) {
            int idx = tid + l * 256;       // 0..1023
            int r = idx >> 4;              // 0..63
            int k = idx & 15;
            int rg = r0 + r;
            int c = kk + k;
            float w;
            if (rg < DDIM)            w = wq[rg * CDIM + c];
            else if (rg < 2 * DDIM)   w = wk[(rg - DDIM) * CDIM + c];
            else                      w = wv[(rg - 2 * DDIM) * CDIM + c];
            Ws[k][r] = w;
        }
        // Load X tile (n contiguous -> coalesced)
#pragma unroll
        for (int l = 0; l < 4; l++) {
            int idx = tid + l * 256;
            int k = idx >> 6;              // 0..15
            int n = idx & 63;
            Xs[k][n] = xb[(size_t)(kk + k) * NPIX + n0 + n];
        }
        __syncthreads();

#pragma unroll
        for (int k = 0; k < 16; k++) {
            float av[4], bv4[4];
#pragma unroll
            for (int i = 0; i < 4; i++) av[i] = Ws[k][ty * 4 + i];
#pragma unroll
            for (int j = 0; j < 4; j++) bv4[j] = Xs[k][tx * 4 + j];
#pragma unroll
            for (int i = 0; i < 4; i++)
#pragma unroll
                for (int j = 0; j < 4; j++)
                    acc[i][j] = fmaf(av[i], bv4[j], acc[i][j]);
        }
        __syncthreads();
    }

    // Bias + store to g_qkv[b][n][r]
#pragma unroll
    for (int i = 0; i < 4; i++) {
        int rg = r0 + ty * 4 + i;
        float bias;
        if (rg < DDIM)          bias = bq[rg];
        else if (rg < 2 * DDIM) bias = bk[rg - DDIM];
        else                    bias = bv[rg - 2 * DDIM];
#pragma unroll
        for (int j = 0; j < 4; j++) {
            int n = n0 + tx * 4 + j;
            g_qkv[((size_t)b * NPIX + n) * RTOT + rg] = acc[i][j] + bias;
        }
    }
}

// ---------------------------------------------------------------------------
// Kernel 2: fused flash attention (online softmax) + gamma residual + LayerNorm.
// Block = 64 queries of one batch. 256 threads; thread t owns channel c=t and
// a 64-deep register accumulator Oc[q]. 64-key tiles.
// ---------------------------------------------------------------------------
__global__ __launch_bounds__(256, 2) void attn_kernel(
    const float* __restrict__ x,
    const float* __restrict__ gamma,
    const float* __restrict__ ln_w,
    const float* __restrict__ ln_b,
    float* __restrict__ out)
{
    __shared__ float Qs[MQ][33];       // conflict-free scalar reads
    __shared__ float Ks[TK][33];
    __shared__ float Ps[MQ][68];       // 68 % 4 == 0 -> rows 16B aligned for LDS.128
    __shared__ float mstat[MQ], lstat[MQ], alpha_s[MQ];
    __shared__ float wsum[MQ][8], wsq[MQ][8];

    const int b  = blockIdx.y;
    const int n0 = blockIdx.x * MQ;
    const int tid  = threadIdx.x;
    const int lane = tid & 31;
    const int warp = tid >> 5;
    const float NEG_INF = __int_as_float(0xff800000);

    const float* qkv_b = g_qkv + (size_t)b * NPIX * RTOT;

    // Load Q tile, fold scale*log2e
    for (int idx = tid; idx < MQ * DDIM; idx += 256) {
        int q = idx >> 5, d = idx & 31;
        Qs[q][d] = qkv_b[(size_t)(n0 + q) * RTOT + d] * SCALE_LOG2E;
    }
    if (tid < MQ) { mstat[tid] = NEG_INF; lstat[tid] = 0.0f; }

    float Oc[MQ];
#pragma unroll
    for (int q = 0; q < MQ; q++) Oc[q] = 0.0f;
    __syncthreads();

    const int qg = (tid >> 4) * 4;    // score microtile: 4 queries
    const int kg = (tid & 15) * 4;    //                  4 keys
    const int sq = tid >> 2;          // stats: 4 threads per query row
    const int sp = tid & 3;
    const int c  = tid;               // owned channel

    for (int kt = 0; kt < NPIX / TK; kt++) {
        const int k0 = kt * TK;
        // Load K tile (coalesced: d contiguous)
        for (int idx = tid; idx < TK * DDIM; idx += 256) {
            int kk = idx >> 5, d = idx & 31;
            Ks[kk][d] = qkv_b[(size_t)(k0 + kk) * RTOT + DDIM + d];
        }
        __syncthreads();

        // S = Q K^T (already in log2 domain)
        {
            float acc[4][4];
#pragma unroll
            for (int i = 0; i < 4; i++)
#pragma unroll
                for (int j = 0; j < 4; j++) acc[i][j] = 0.0f;
#pragma unroll 8
            for (int d = 0; d < DDIM; d++) {
                float qv[4], kv[4];
#pragma unroll
                for (int i = 0; i < 4; i++) qv[i] = Qs[qg + i][d];
#pragma unroll
                for (int j = 0; j < 4; j++) kv[j] = Ks[kg + j][d];
#pragma unroll
                for (int i = 0; i < 4; i++)
#pragma unroll
                    for (int j = 0; j < 4; j++)
                        acc[i][j] = fmaf(qv[i], kv[j], acc[i][j]);
            }
#pragma unroll
            for (int i = 0; i < 4; i++) {
                float4 v = make_float4(acc[i][0], acc[i][1], acc[i][2], acc[i][3]);
                *reinterpret_cast<float4*>(&Ps[qg + i][kg]) = v;
            }
        }
        __syncthreads();

        // Row stats: max, exp2, sum (4 threads per row)
        {
            float m = NEG_INF;
#pragma unroll
            for (int t = 0; t < 16; t++) m = fmaxf(m, Ps[sq][sp * 16 + t]);
            m = fmaxf(m, __shfl_xor_sync(0xffffffffu, m, 1));
            m = fmaxf(m, __shfl_xor_sync(0xffffffffu, m, 2));
            float m_old = mstat[sq];
            float m_new = fmaxf(m_old, m);
            float ls = 0.0f;
#pragma unroll
            for (int t = 0; t < 16; t++) {
                float p = ex2f(Ps[sq][sp * 16 + t] - m_new);
                Ps[sq][sp * 16 + t] = p;
                ls += p;
            }
            ls += __shfl_xor_sync(0xffffffffu, ls, 1);
            ls += __shfl_xor_sync(0xffffffffu, ls, 2);
            if (sp == 0) {
                float al = ex2f(m_old - m_new);   // first tile: ex2(-inf) = 0
                alpha_s[sq] = al;
                lstat[sq] = lstat[sq] * al + ls;
                mstat[sq] = m_new;
            }
        }
        __syncthreads();

        // Rescale accumulators, then O += P * V
#pragma unroll
        for (int q = 0; q < MQ; q++) Oc[q] *= alpha_s[q];

        const float* vcol = qkv_b + (size_t)k0 * RTOT + 2 * DDIM + c;
#pragma unroll 1
        for (int kc = 0; kc < TK; kc += 8) {
            float vr[8];
#pragma unroll
            for (int j = 0; j < 8; j++)
                vr[j] = vcol[(size_t)(kc + j) * RTOT];   // coalesced across threads
#pragma unroll
            for (int q = 0; q < MQ; q++) {
                const float4* pr = reinterpret_cast<const float4*>(&Ps[q][kc]);
                float4 pa = pr[0], pb = pr[1];           // broadcast LDS.128
                float o = Oc[q];
                o = fmaf(pa.x, vr[0], o); o = fmaf(pa.y, vr[1], o);
                o = fmaf(pa.z, vr[2], o); o = fmaf(pa.w, vr[3], o);
                o = fmaf(pb.x, vr[4], o); o = fmaf(pb.y, vr[5], o);
                o = fmaf(pb.z, vr[6], o); o = fmaf(pb.w, vr[7], o);
                Oc[q] = o;
            }
        }
        __syncthreads();
    }

    // ---- Finalize: normalize, gamma residual ----
    if (tid < MQ) alpha_s[tid] = 1.0f / lstat[tid];    // reuse as 1/l
    __syncthreads();

    const float g = gamma[0];
    const float* xrow = x + ((size_t)b * CDIM + c) * NPIX + n0;
#pragma unroll
    for (int q4 = 0; q4 < MQ / 4; q4++) {
        float4 xv = reinterpret_cast<const float4*>(xrow)[q4];
        Oc[4 * q4 + 0] = fmaf(g * alpha_s[4 * q4 + 0], Oc[4 * q4 + 0], xv.x);
        Oc[4 * q4 + 1] = fmaf(g * alpha_s[4 * q4 + 1], Oc[4 * q4 + 1], xv.y);
        Oc[4 * q4 + 2] = fmaf(g * alpha_s[4 * q4 + 2], Oc[4 * q4 + 2], xv.z);
        Oc[4 * q4 + 3] = fmaf(g * alpha_s[4 * q4 + 3], Oc[4 * q4 + 3], xv.w);
    }

    // ---- LayerNorm over channels: block reduction per query ----
#pragma unroll
    for (int q = 0; q < MQ; q++) {
        float v = Oc[q];
        float s = v, s2 = v * v;
#pragma unroll
        for (int off = 16; off; off >>= 1) {
            s  += __shfl_xor_sync(0xffffffffu, s,  off);
            s2 += __shfl_xor_sync(0xffffffffu, s2, off);
        }
        if (lane == 0) { wsum[q][warp] = s; wsq[q][warp] = s2; }
    }
    __syncthreads();
    if (tid < MQ) {
        float s = 0.0f, s2 = 0.0f;
#pragma unroll
        for (int w = 0; w < 8; w++) { s += wsum[tid][w]; s2 += wsq[tid][w]; }
        float mu  = s * (1.0f / CDIM);
        float var = s2 * (1.0f / CDIM) - mu * mu;
        mstat[tid] = mu;                 // reuse for mean
        lstat[tid] = rsqrtf(var + LN_EPS);  // reuse for rstd
    }
    __syncthreads();

    const float lw = ln_w[c], lb = ln_b[c];
    float* orow = out + ((size_t)b * CDIM + c) * NPIX + n0;
#pragma unroll
    for (int q4 = 0; q4 < MQ / 4; q4++) {
        float4 y;
        y.x = fmaf((Oc[4 * q4 + 0] - mstat[4 * q4 + 0]) * lstat[4 * q4 + 0], lw, lb);
        y.y = fmaf((Oc[4 * q4 + 1] - mstat[4 * q4 + 1]) * lstat[4 * q4 + 1], lw, lb);
        y.z = fmaf((Oc[4 * q4 + 2] - mstat[4 * q4 + 2]) * lstat[4 * q4 + 2], lw, lb);
        y.w = fmaf((Oc[4 * q4 + 3] - mstat[4 * q4 + 3]) * lstat[4 * q4 + 3], lw, lb);
        reinterpret_cast<float4*>(orow)[q4] = y;
    }
}

// ---------------------------------------------------------------------------
extern "C" void kernel_launch(void* const* d_in, const int* in_sizes, int n_in,
                              void* d_out, int out_size)
{
    const float* x     = (const float*)d_in[0];
    const float* wq    = (const float*)d_in[1];
    const float* bq    = (const float*)d_in[2];
    const float* wk    = (const float*)d_in[3];
    const float* bk    = (const float*)d_in[4];
    const float* wv    = (const float*)d_in[5];
    const float* bv    = (const float*)d_in[6];
    const float* gamma = (const float*)d_in[7];
    const float* ln_w  = (const float*)d_in[8];
    const float* ln_b  = (const float*)d_in[9];
    float* out = (float*)d_out;

    qkv_kernel<<<dim3(RTOT / 64, NPIX / 64, BATCH), 256>>>(x, wq, bq, wk, bk, wv, bv);
    attn_kernel<<<dim3(NPIX / MQ, BATCH), 256>>>(x, gamma, ln_w, ln_b, out);
}

// round 4
// speedup vs baseline: 5.7072x; 5.7072x over previous
#include <cuda_runtime.h>
#include <cuda_bf16.h>
#include <cstdint>

// ---------------- problem constants ----------------
#define BATCH 4
#define CDIM  256
#define DDIM  32
#define NPIX  4096
#define LN_EPS 1e-5f
#define SCALE_LOG2E 0.2550348639f   // (1/sqrt(32)) * log2(e)

#define MQ 128                      // queries per CTA
#define TK 128                      // keys per tile
#define NTILES (NPIX / TK)          // 32

// ---------------- scratch (bf16, MMA-friendly layouts) ----------------
__device__ __nv_bfloat16 g_q[(size_t)BATCH * NPIX * DDIM];   // [b][n][d], pre-scaled
__device__ __nv_bfloat16 g_k[(size_t)BATCH * DDIM * NPIX];   // [b][d][n]
__device__ __nv_bfloat16 g_v[(size_t)BATCH * NPIX * CDIM];   // [b][n][c]

// ---------------- smem layout (bytes, dynamic) ----------------
// QS: 128 rows x 80B   (64B data + pad)      [0,     10240)
// KS: 32  rows x 272B  (256B data + pad)     [10240, 18944)
// VS: 128 rows x 528B  (512B data + pad)     [18944, 86528)
// OutS overlay: 128 x 516B bf16              [0,     66048)
#define QS_OFF   0
#define KS_OFF   10240
#define VS_OFF   18944
#define OUTS_OFF 0
#define WS_OFF   86528
#define WQ_OFF   88576
#define MST_OFF  90624
#define LSTD_OFF 90880
#define SMEM_DYN 91136

// ---------------- PTX helpers (sm_100 base-target safe) ----------------
__device__ __forceinline__ uint32_t smem_u32(const void* p) {
    uint32_t a;
    asm("{ .reg .u64 t; cvta.to.shared.u64 t, %1; cvt.u32.u64 %0, t; }" : "=r"(a) : "l"(p));
    return a;
}
__device__ __forceinline__ float ex2f(float v) {
    float y; asm("ex2.approx.ftz.f32 %0, %1;" : "=f"(y) : "f"(v)); return y;
}
__device__ __forceinline__ void ldsm4(uint32_t* r, uint32_t addr) {
    asm volatile("ldmatrix.sync.aligned.m8n8.x4.shared.b16 {%0,%1,%2,%3}, [%4];"
                 : "=r"(r[0]), "=r"(r[1]), "=r"(r[2]), "=r"(r[3]) : "r"(addr));
}
__device__ __forceinline__ void ldsm4t(uint32_t* r, uint32_t addr) {
    asm volatile("ldmatrix.sync.aligned.m8n8.x4.trans.shared.b16 {%0,%1,%2,%3}, [%4];"
                 : "=r"(r[0]), "=r"(r[1]), "=r"(r[2]), "=r"(r[3]) : "r"(addr));
}
__device__ __forceinline__ void mma16816(float* c, const uint32_t* a, const uint32_t* b) {
    asm volatile("mma.sync.aligned.m16n8k16.row.col.f32.bf16.bf16.f32 "
                 "{%0,%1,%2,%3}, {%4,%5,%6,%7}, {%8,%9}, {%0,%1,%2,%3};"
                 : "+f"(c[0]), "+f"(c[1]), "+f"(c[2]), "+f"(c[3])
                 : "r"(a[0]), "r"(a[1]), "r"(a[2]), "r"(a[3]), "r"(b[0]), "r"(b[1]));
}
#define CP_ASYNC16(dst, src) \
    asm volatile("cp.async.cg.shared.global [%0], [%1], 16;" :: "r"(dst), "l"(src))
#define CP_COMMIT() asm volatile("cp.async.commit_group;" ::: "memory")
#define CP_WAIT0()  asm volatile("cp.async.wait_group 0;" ::: "memory")
#define STS32(addr, a) \
    asm volatile("st.shared.b32 [%0], %1;" :: "r"(addr), "r"(a) : "memory")
// pack {hi:lo} bf16x2
#define CVT_BF16X2(res, lo, hi) \
    asm("cvt.rn.bf16x2.f32 %0, %1, %2;" : "=r"(res) : "f"(hi), "f"(lo))

// ---------------------------------------------------------------------------
// Kernel 1: QKV projection -> bf16 scratch (MMA layouts).
// ---------------------------------------------------------------------------
__global__ __launch_bounds__(256) void qkv_kernel(
    const float* __restrict__ x,
    const float* __restrict__ wq, const float* __restrict__ bq,
    const float* __restrict__ wk, const float* __restrict__ bk,
    const float* __restrict__ wv, const float* __restrict__ bv)
{
    __shared__ float Ws[16][68];
    __shared__ float Xs[16][132];

    const int b  = blockIdx.z;
    const int r0 = blockIdx.x * 64;
    const int n0 = blockIdx.y * 128;
    const int tid = threadIdx.x;
    const int tx = tid & 31, ty = tid >> 5;
    const float* xb = x + (size_t)b * CDIM * NPIX;

    float acc[8][4];
#pragma unroll
    for (int i = 0; i < 8; i++)
#pragma unroll
        for (int j = 0; j < 4; j++) acc[i][j] = 0.0f;

    for (int kk = 0; kk < CDIM; kk += 16) {
#pragma unroll
        for (int l = 0; l < 4; l++) {
            int idx = tid + l * 256;
            int r = idx >> 4, k = idx & 15;
            int rg = r0 + r, c = kk + k;
            float w;
            if (rg < DDIM)            w = wq[rg * CDIM + c];
            else if (rg < 2 * DDIM)   w = wk[(rg - DDIM) * CDIM + c];
            else                      w = wv[(rg - 2 * DDIM) * CDIM + c];
            Ws[k][r] = w;
        }
#pragma unroll
        for (int l = 0; l < 8; l++) {
            int idx = tid + l * 256;
            int k = idx >> 7, n = idx & 127;
            Xs[k][n] = xb[(size_t)(kk + k) * NPIX + n0 + n];
        }
        __syncthreads();
#pragma unroll
        for (int k = 0; k < 16; k++) {
            float4 a0 = *reinterpret_cast<const float4*>(&Ws[k][ty * 8]);
            float4 a1 = *reinterpret_cast<const float4*>(&Ws[k][ty * 8 + 4]);
            float4 b0 = *reinterpret_cast<const float4*>(&Xs[k][tx * 4]);
            float av[8] = {a0.x, a0.y, a0.z, a0.w, a1.x, a1.y, a1.z, a1.w};
            float bvv[4] = {b0.x, b0.y, b0.z, b0.w};
#pragma unroll
            for (int i = 0; i < 8; i++)
#pragma unroll
                for (int j = 0; j < 4; j++)
                    acc[i][j] = fmaf(av[i], bvv[j], acc[i][j]);
        }
        __syncthreads();
    }

#pragma unroll
    for (int i = 0; i < 8; i++) {
        int rg = r0 + ty * 8 + i;
        float bias;
        if (rg < DDIM)          bias = bq[rg];
        else if (rg < 2 * DDIM) bias = bk[rg - DDIM];
        else                    bias = bv[rg - 2 * DDIM];
#pragma unroll
        for (int j = 0; j < 4; j++) {
            int n = n0 + tx * 4 + j;
            float val = acc[i][j] + bias;
            if (rg < DDIM)
                g_q[((size_t)b * NPIX + n) * DDIM + rg] = __float2bfloat16(val * SCALE_LOG2E);
            else if (rg < 2 * DDIM)
                g_k[((size_t)b * DDIM + (rg - DDIM)) * NPIX + n] = __float2bfloat16(val);
            else
                g_v[((size_t)b * NPIX + n) * CDIM + (rg - 2 * DDIM)] = __float2bfloat16(val);
        }
    }
}

// ---------------------------------------------------------------------------
// Kernel 2: mma.sync bf16 flash attention + gamma residual + LayerNorm.
// 128 queries/CTA, 8 warps x 16 query rows, O[16x256] in registers per warp.
// ---------------------------------------------------------------------------
__global__ __launch_bounds__(256, 1) void attn_kernel(
    const float* __restrict__ x,
    const float* __restrict__ gamma,
    const float* __restrict__ ln_w,
    const float* __restrict__ ln_b,
    float* __restrict__ out)
{
    extern __shared__ char dsm[];
    const uint32_t sb = smem_u32(dsm);

    const int b  = blockIdx.y;
    const int n0 = blockIdx.x * MQ;
    const int tid  = threadIdx.x;
    const int lane = tid & 31;
    const int warp = tid >> 5;
    const int qg = lane >> 2;          // quad row 0..7
    const int qt = lane & 3;           // quad col 0..3
    const int wbase = warp * 16;       // query rows [wbase, wbase+16)

    const __nv_bfloat16* qb = g_q + (size_t)b * NPIX * DDIM;
    const __nv_bfloat16* kb = g_k + (size_t)b * DDIM * NPIX;
    const __nv_bfloat16* vb = g_v + (size_t)b * NPIX * CDIM;

    // ---- stage Q tile (128 x 64B) via cp.async ----
#pragma unroll
    for (int i = 0; i < 2; i++) {
        int idx = tid + i * 256;
        int row = idx >> 2, ch = idx & 3;
        CP_ASYNC16(sb + QS_OFF + row * 80 + ch * 16,
                   (const char*)(qb + (size_t)(n0 + row) * DDIM) + ch * 16);
    }
    CP_COMMIT(); CP_WAIT0();
    __syncthreads();

    // ---- load Q A-fragments (persist whole kernel) ----
    uint32_t qa[2][4];
#pragma unroll
    for (int ks = 0; ks < 2; ks++) {
        int r  = wbase + (lane & 7) + ((lane >> 3) & 1) * 8;
        int cb = ks * 32 + (lane >> 4) * 16;
        ldsm4(qa[ks], sb + QS_OFF + r * 80 + cb);
    }

    // O accumulators: 32 n-blocks x 4
    float o[32][4];
#pragma unroll
    for (int nb = 0; nb < 32; nb++)
#pragma unroll
        for (int j = 0; j < 4; j++) o[nb][j] = 0.0f;

    float lsum0 = 0.0f, lsum1 = 0.0f;
    const uint32_t kaddr = sb + KS_OFF + lane * 272;
    const uint32_t vbase = sb + VS_OFF + (lane & 15) * 528 + (lane >> 4) * 16;

    for (int kt = 0; kt < NTILES; kt++) {
        const int k0 = kt * TK;
        __syncthreads();   // previous tile's smem fully consumed
        // K tile: 32 rows x 256B
#pragma unroll
        for (int i = 0; i < 2; i++) {
            int idx = tid + i * 256;
            int d = idx >> 4, ch = idx & 15;
            CP_ASYNC16(sb + KS_OFF + d * 272 + ch * 16,
                       (const char*)(kb + (size_t)d * NPIX + k0) + ch * 16);
        }
        // V tile: 128 rows x 512B
#pragma unroll
        for (int i = 0; i < 16; i++) {
            int idx = tid + i * 256;
            int row = idx >> 5, ch = idx & 31;
            CP_ASYNC16(sb + VS_OFF + row * 528 + ch * 16,
                       (const char*)(vb + (size_t)(k0 + row) * CDIM) + ch * 16);
        }
        CP_COMMIT(); CP_WAIT0();
        __syncthreads();

        // ---- GEMM1 + softmax, fused per 8-key block; pack P fragments ----
        uint32_t P[8][4];
#pragma unroll
        for (int jp = 0; jp < 8; jp++) {
#pragma unroll
            for (int jh = 0; jh < 2; jh++) {
                const int j = jp * 2 + jh;
                float c[4] = {0.0f, 0.0f, 0.0f, 0.0f};
                uint32_t bk4[4];
                ldsm4t(bk4, kaddr + j * 16);
                mma16816(c, qa[0], bk4);
                mma16816(c, qa[1], bk4 + 2);
                float e0 = ex2f(c[0]), e1 = ex2f(c[1]);
                float e2 = ex2f(c[2]), e3 = ex2f(c[3]);
                lsum0 += e0 + e1;
                lsum1 += e2 + e3;
                CVT_BF16X2(P[jp][jh * 2 + 0], e0, e1);   // row qg,   keys lo-pair
                CVT_BF16X2(P[jp][jh * 2 + 1], e2, e3);   // row qg+8
            }
        }

        // ---- GEMM2: O += P * V ----
#pragma unroll
        for (int ks = 0; ks < 8; ks++) {
            const uint32_t va = vbase + ks * 8448;       // 16 rows * 528B
#pragma unroll
            for (int jp2 = 0; jp2 < 16; jp2++) {
                uint32_t bv4[4];
                ldsm4t(bv4, va + jp2 * 32);
                mma16816(o[2 * jp2],     P[ks], bv4);
                mma16816(o[2 * jp2 + 1], P[ks], bv4 + 2);
            }
        }
    }

    // ---- finalize row sums (reduce over quad lanes) ----
    lsum0 += __shfl_xor_sync(0xffffffffu, lsum0, 1);
    lsum0 += __shfl_xor_sync(0xffffffffu, lsum0, 2);
    lsum1 += __shfl_xor_sync(0xffffffffu, lsum1, 1);
    lsum1 += __shfl_xor_sync(0xffffffffu, lsum1, 2);
    const float gam = gamma[0];
    const float scl0 = gam / lsum0;
    const float scl1 = gam / lsum1;

    __syncthreads();   // done reading Q/K/V smem; safe to overlay OutS

    // ---- write scaled O to OutS (bf16, 516B row stride) ----
    {
        const uint32_t a0base = sb + OUTS_OFF + (uint32_t)(wbase + qg) * 516u + (uint32_t)(2 * qt) * 2u;
#pragma unroll
        for (int nb = 0; nb < 32; nb++) {
            uint32_t p0, p1;
            CVT_BF16X2(p0, o[nb][0] * scl0, o[nb][1] * scl0);
            CVT_BF16X2(p1, o[nb][2] * scl1, o[nb][3] * scl1);
            STS32(a0base + (uint32_t)nb * 16u, p0);
            STS32(a0base + 8u * 516u + (uint32_t)nb * 16u, p1);
        }
    }
    __syncthreads();

    // ---- residual + LayerNorm: thread = channel, two halves of 64 pixels ----
    const int c = tid;
    const float lw = ln_w[c], lb = ln_b[c];
    float* wsum = reinterpret_cast<float*>(dsm + WS_OFF);
    float* wsq  = reinterpret_cast<float*>(dsm + WQ_OFF);
    float* mst  = reinterpret_cast<float*>(dsm + MST_OFF);
    float* lstd = reinterpret_cast<float*>(dsm + LSTD_OFF);
    const __nv_bfloat16* outs = reinterpret_cast<const __nv_bfloat16*>(dsm + OUTS_OFF);

    for (int hh = 0; hh < 2; hh++) {
        const int q0 = hh * 64;
        float Oc[64];
        const float* xrow = x + ((size_t)b * CDIM + c) * NPIX + n0 + q0;
#pragma unroll
        for (int j4 = 0; j4 < 16; j4++) {
            float4 xv = reinterpret_cast<const float4*>(xrow)[j4];
            float o0 = __bfloat162float(outs[(size_t)(q0 + 4 * j4 + 0) * 258 + c]);
            float o1 = __bfloat162float(outs[(size_t)(q0 + 4 * j4 + 1) * 258 + c]);
            float o2 = __bfloat162float(outs[(size_t)(q0 + 4 * j4 + 2) * 258 + c]);
            float o3 = __bfloat162float(outs[(size_t)(q0 + 4 * j4 + 3) * 258 + c]);
            Oc[4 * j4 + 0] = o0 + xv.x;
            Oc[4 * j4 + 1] = o1 + xv.y;
            Oc[4 * j4 + 2] = o2 + xv.z;
            Oc[4 * j4 + 3] = o3 + xv.w;
        }
#pragma unroll
        for (int q = 0; q < 64; q++) {
            float v = Oc[q];
            float s = v, s2 = v * v;
#pragma unroll
            for (int off = 16; off; off >>= 1) {
                s  += __shfl_xor_sync(0xffffffffu, s,  off);
                s2 += __shfl_xor_sync(0xffffffffu, s2, off);
            }
            if (lane == 0) { wsum[q * 8 + warp] = s; wsq[q * 8 + warp] = s2; }
        }
        __syncthreads();
        if (tid < 64) {
            float s = 0.0f, s2 = 0.0f;
#pragma unroll
            for (int w = 0; w < 8; w++) { s += wsum[tid * 8 + w]; s2 += wsq[tid * 8 + w]; }
            float mu  = s * (1.0f / CDIM);
            float var = s2 * (1.0f / CDIM) - mu * mu;
            mst[tid]  = mu;
            lstd[tid] = rsqrtf(var + LN_EPS);
        }
        __syncthreads();
        float* orow = out + ((size_t)b * CDIM + c) * NPIX + n0 + q0;
#pragma unroll
        for (int j4 = 0; j4 < 16; j4++) {
            float4 y;
            y.x = fmaf((Oc[4*j4 + 0] - mst[4*j4 + 0]) * lstd[4*j4 + 0], lw, lb);
            y.y = fmaf((Oc[4*j4 + 1] - mst[4*j4 + 1]) * lstd[4*j4 + 1], lw, lb);
            y.z = fmaf((Oc[4*j4 + 2] - mst[4*j4 + 2]) * lstd[4*j4 + 2], lw, lb);
            y.w = fmaf((Oc[4*j4 + 3] - mst[4*j4 + 3]) * lstd[4*j4 + 3], lw, lb);
            reinterpret_cast<float4*>(orow)[j4] = y;
        }
        __syncthreads();
    }
}

// ---------------------------------------------------------------------------
extern "C" void kernel_launch(void* const* d_in, const int* in_sizes, int n_in,
                              void* d_out, int out_size)
{
    const float* x     = (const float*)d_in[0];
    const float* wq    = (const float*)d_in[1];
    const float* bq    = (const float*)d_in[2];
    const float* wk    = (const float*)d_in[3];
    const float* bk    = (const float*)d_in[4];
    const float* wv    = (const float*)d_in[5];
    const float* bv    = (const float*)d_in[6];
    const float* gamma = (const float*)d_in[7];
    const float* ln_w  = (const float*)d_in[8];
    const float* ln_b  = (const float*)d_in[9];
    float* out = (float*)d_out;

    cudaFuncSetAttribute(attn_kernel, cudaFuncAttributeMaxDynamicSharedMemorySize, SMEM_DYN);

    qkv_kernel<<<dim3(320 / 64, NPIX / 128, BATCH), 256>>>(x, wq, bq, wk, bk, wv, bv);
    attn_kernel<<<dim3(NPIX / MQ, BATCH), 256, SMEM_DYN>>>(x, gamma, ln_w, ln_b, out);
}

// round 5
// speedup vs baseline: 8.3588x; 1.4646x over previous
#include <cuda_runtime.h>
#include <cuda_bf16.h>
#include <cstdint>

// ---------------- problem constants ----------------
#define BATCH 4
#define CDIM  256
#define DDIM  32
#define NPIX  4096
#define LN_EPS 1e-5f
#define SCALE_LOG2E 0.2550348639f   // (1/sqrt(32)) * log2(e)

#define MQ 128                      // queries per CTA
#define TK 128                      // keys per tile
#define NTILES (NPIX / TK)          // 32

// ---------------- scratch (bf16, MMA-friendly layouts) ----------------
__device__ __nv_bfloat16 g_q[(size_t)BATCH * NPIX * DDIM];   // [b][n][d], pre-scaled
__device__ __nv_bfloat16 g_k[(size_t)BATCH * DDIM * NPIX];   // [b][d][n]
__device__ __nv_bfloat16 g_v[(size_t)BATCH * NPIX * CDIM];   // [b][n][c]

// ---------------- attn smem layout (bytes, dynamic) ----------------
// QS:  128 x 80B                       [0,      10240)
// KS0: 32 x 272B / VS0: 128 x 528B     [10240,  86528)
// KS1 / VS1 (double buffer)            [86528, 162816)
// OutS overlay (128 x 516B)            [10240,  76288)
#define QS_OFF    0
#define KS_OFF    10240
#define VS_OFF    18944
#define BUFSTRIDE 76288
#define OUTS_OFF  10240
#define WS_OFF    162816
#define WQ_OFF    166912
#define MST_OFF   171008
#define LSTD_OFF  171520
#define SMEM_DYN  172032

// ---------------- PTX helpers (sm_100 base-target safe) ----------------
__device__ __forceinline__ uint32_t smem_u32(const void* p) {
    uint32_t a;
    asm("{ .reg .u64 t; cvta.to.shared.u64 t, %1; cvt.u32.u64 %0, t; }" : "=r"(a) : "l"(p));
    return a;
}
__device__ __forceinline__ float ex2f(float v) {
    float y; asm("ex2.approx.ftz.f32 %0, %1;" : "=f"(y) : "f"(v)); return y;
}
__device__ __forceinline__ void ldsm4(uint32_t* r, uint32_t addr) {
    asm volatile("ldmatrix.sync.aligned.m8n8.x4.shared.b16 {%0,%1,%2,%3}, [%4];"
                 : "=r"(r[0]), "=r"(r[1]), "=r"(r[2]), "=r"(r[3]) : "r"(addr));
}
__device__ __forceinline__ void ldsm4t(uint32_t* r, uint32_t addr) {
    asm volatile("ldmatrix.sync.aligned.m8n8.x4.trans.shared.b16 {%0,%1,%2,%3}, [%4];"
                 : "=r"(r[0]), "=r"(r[1]), "=r"(r[2]), "=r"(r[3]) : "r"(addr));
}
__device__ __forceinline__ void mma16816(float* c, const uint32_t* a, const uint32_t* b) {
    asm volatile("mma.sync.aligned.m16n8k16.row.col.f32.bf16.bf16.f32 "
                 "{%0,%1,%2,%3}, {%4,%5,%6,%7}, {%8,%9}, {%0,%1,%2,%3};"
                 : "+f"(c[0]), "+f"(c[1]), "+f"(c[2]), "+f"(c[3])
                 : "r"(a[0]), "r"(a[1]), "r"(a[2]), "r"(a[3]), "r"(b[0]), "r"(b[1]));
}
#define CP_ASYNC16(dst, src) \
    asm volatile("cp.async.cg.shared.global [%0], [%1], 16;" :: "r"(dst), "l"(src))
#define CP_COMMIT() asm volatile("cp.async.commit_group;" ::: "memory")
#define CP_WAIT0()  asm volatile("cp.async.wait_group 0;" ::: "memory")
#define CP_WAIT1()  asm volatile("cp.async.wait_group 1;" ::: "memory")
#define STS32(addr, a) \
    asm volatile("st.shared.b32 [%0], %1;" :: "r"(addr), "r"(a) : "memory")
#define STS16(addr, h) \
    asm volatile("st.shared.b16 [%0], %1;" :: "r"(addr), "h"(h) : "memory")
#define LDS32(res, addr) \
    asm volatile("ld.shared.b32 %0, [%1];" : "=r"(res) : "r"(addr))
#define LDS16(res, addr) \
    asm volatile("ld.shared.b16 %0, [%1];" : "=h"(res) : "r"(addr))
// pack {hi:lo} bf16x2
#define CVT_BF16X2(res, lo, hi) \
    asm("cvt.rn.bf16x2.f32 %0, %1, %2;" : "=r"(res) : "f"(hi), "f"(lo))

__device__ __forceinline__ uint16_t bf16_bits(float v) {
    uint32_t p; CVT_BF16X2(p, v, 0.0f); return (uint16_t)(p & 0xFFFFu);
}

// ---------------------------------------------------------------------------
// Kernel 1: QKV projection via bf16 mma.sync.
// CTA: 64 r-rows x 128 n-cols, 256 threads / 8 warps (4 rgroups x 2 nhalves).
// ---------------------------------------------------------------------------
#define WT_OFF 0        // 64 rows x 80B  = 5120
#define XT_OFF 5120     // 32 rows x 272B = 8704  (end 13824)
// T overlay (output transpose): 128 n x 132B = 16896

__global__ __launch_bounds__(256) void qkv_kernel(
    const float* __restrict__ x,
    const float* __restrict__ wq, const float* __restrict__ bq,
    const float* __restrict__ wk, const float* __restrict__ bk,
    const float* __restrict__ wv, const float* __restrict__ bv)
{
    __shared__ __align__(16) char qsm[16896];
    const uint32_t sb = smem_u32(qsm);

    const int b  = blockIdx.z;
    const int n0 = blockIdx.x * 128;
    const int r0 = blockIdx.y * 64;
    const int tid  = threadIdx.x;
    const int lane = tid & 31;
    const int warp = tid >> 5;
    const int rgrp  = (warp & 3) * 16;
    const int nhalf = (warp >> 2) * 64;
    const int qg = lane >> 2, qt = lane & 3;
    const float* xb = x + (size_t)b * CDIM * NPIX;

    float acc[8][4];
#pragma unroll
    for (int i = 0; i < 8; i++)
#pragma unroll
        for (int j = 0; j < 4; j++) acc[i][j] = 0.0f;

    for (int kk = 0; kk < CDIM; kk += 32) {
        // W tile: 64 r x 32 c fp32 -> bf16 (pairs)
#pragma unroll
        for (int l = 0; l < 4; l++) {
            int idx = tid + l * 256;
            int r = idx >> 4, cp = (idx & 15) * 2;
            int rg = r0 + r, c = kk + cp;
            const float* ws;
            if (rg < DDIM)            ws = wq + rg * CDIM + c;
            else if (rg < 2 * DDIM)   ws = wk + (rg - DDIM) * CDIM + c;
            else                      ws = wv + (rg - 2 * DDIM) * CDIM + c;
            float2 w2 = *reinterpret_cast<const float2*>(ws);
            uint32_t pw; CVT_BF16X2(pw, w2.x, w2.y);
            STS32(sb + WT_OFF + r * 80 + cp * 2, pw);
        }
        // X tile: 32 k x 128 n fp32 -> bf16 (pairs, coalesced)
#pragma unroll
        for (int l = 0; l < 8; l++) {
            int idx = tid + l * 256;
            int k = idx >> 6, np = (idx & 63) * 2;
            float2 x2 = *reinterpret_cast<const float2*>(xb + (size_t)(kk + k) * NPIX + n0 + np);
            uint32_t px; CVT_BF16X2(px, x2.x, x2.y);
            STS32(sb + XT_OFF + k * 272 + np * 2, px);
        }
        __syncthreads();

        uint32_t wa[2][4];
        {
            int r = rgrp + (lane & 7) + ((lane >> 3) & 1) * 8;
            int cb = (lane >> 4) * 16;
            ldsm4(wa[0], sb + WT_OFF + r * 80 + cb);
            ldsm4(wa[1], sb + WT_OFF + r * 80 + 32 + cb);
        }
        const uint32_t xaddr = sb + XT_OFF + lane * 272 + nhalf * 2;
#pragma unroll
        for (int nb = 0; nb < 8; nb++) {
            uint32_t bx[4];
            ldsm4t(bx, xaddr + nb * 16);
            mma16816(acc[nb], wa[0], bx);
            mma16816(acc[nb], wa[1], bx + 2);
        }
        __syncthreads();
    }

    // ---- bias + stage into T[n][r] (bf16) ----
#pragma unroll
    for (int half = 0; half < 2; half++) {
        int rl = rgrp + qg + half * 8;
        int rg = r0 + rl;
        float bias;
        if (rg < DDIM)          bias = bq[rg];
        else if (rg < 2 * DDIM) bias = bk[rg - DDIM];
        else                    bias = bv[rg - 2 * DDIM];
        float mult = (rg < DDIM) ? SCALE_LOG2E : 1.0f;
#pragma unroll
        for (int nb = 0; nb < 8; nb++) {
            int nl = nhalf + nb * 8 + qt * 2;
            float v0 = (acc[nb][half * 2 + 0] + bias) * mult;
            float v1 = (acc[nb][half * 2 + 1] + bias) * mult;
            STS16(sb + nl * 132 + rl * 2, bf16_bits(v0));
            STS16(sb + (nl + 1) * 132 + rl * 2, bf16_bits(v1));
        }
    }
    __syncthreads();

    // ---- coalesced global stores ----
    if (r0 == 0) {
        // q rows 0..31 -> g_q[b][n][d]  (d contiguous)
#pragma unroll
        for (int l = 0; l < 8; l++) {
            int idx = tid + l * 256;
            int n = idx >> 4, rp = (idx & 15) * 2;
            uint32_t w; LDS32(w, sb + n * 132 + rp * 2);
            *reinterpret_cast<uint32_t*>(&g_q[((size_t)b * NPIX + n0 + n) * DDIM + rp]) = w;
        }
        // k rows 32..63 -> g_k[b][d][n]  (n contiguous)
#pragma unroll
        for (int l = 0; l < 8; l++) {
            int idx = tid + l * 256;
            int r = 32 + (idx >> 6), np = (idx & 63) * 2;
            uint16_t h0, h1;
            LDS16(h0, sb + np * 132 + r * 2);
            LDS16(h1, sb + (np + 1) * 132 + r * 2);
            uint32_t w = (uint32_t)h0 | ((uint32_t)h1 << 16);
            *reinterpret_cast<uint32_t*>(&g_k[((size_t)b * DDIM + (r - 32)) * NPIX + n0 + np]) = w;
        }
    } else {
        // v channels [r0-64, r0) -> g_v[b][n][c]  (c contiguous)
#pragma unroll
        for (int l = 0; l < 16; l++) {
            int idx = tid + l * 256;
            int n = idx >> 5, cp = (idx & 31) * 2;
            uint32_t w; LDS32(w, sb + n * 132 + cp * 2);
            *reinterpret_cast<uint32_t*>(&g_v[((size_t)b * NPIX + n0 + n) * CDIM + (r0 - 64) + cp]) = w;
        }
    }
}

// ---------------------------------------------------------------------------
// Kernel 2: mma.sync bf16 flash attention + gamma residual + LayerNorm.
// 512 threads / 16 warps: warp = (qgrp 0..7, chalf 0..1).
// Each warp: 16 queries x 128 channels (o = 64 regs). Double-buffered K/V.
// ---------------------------------------------------------------------------
__global__ __launch_bounds__(512, 1) void attn_kernel(
    const float* __restrict__ x,
    const float* __restrict__ gamma,
    const float* __restrict__ ln_w,
    const float* __restrict__ ln_b,
    float* __restrict__ out)
{
    extern __shared__ char dsm[];
    const uint32_t sb = smem_u32(dsm);

    const int b  = blockIdx.y;
    const int n0 = blockIdx.x * MQ;
    const int tid  = threadIdx.x;
    const int lane = tid & 31;
    const int warp = tid >> 5;
    const int qgrp  = warp & 7;
    const int chalf = warp >> 3;
    const int wbase = qgrp * 16;
    const int qg = lane >> 2, qt = lane & 3;

    const __nv_bfloat16* qb = g_q + (size_t)b * NPIX * DDIM;
    const __nv_bfloat16* kb = g_k + (size_t)b * DDIM * NPIX;
    const __nv_bfloat16* vb = g_v + (size_t)b * NPIX * CDIM;

    // ---- prologue: Q + tile0 into buffer 0 ----
    {
        int row = tid >> 2, ch = tid & 3;
        CP_ASYNC16(sb + QS_OFF + row * 80 + ch * 16,
                   (const char*)(qb + (size_t)(n0 + row) * DDIM) + ch * 16);
    }
    {
        int d = tid >> 4, ch = tid & 15;
        CP_ASYNC16(sb + KS_OFF + d * 272 + ch * 16,
                   (const char*)(kb + (size_t)d * NPIX) + ch * 16);
#pragma unroll
        for (int i = 0; i < 8; i++) {
            int idx = tid + i * 512;
            int row = idx >> 5, c2 = idx & 31;
            CP_ASYNC16(sb + VS_OFF + row * 528 + c2 * 16,
                       (const char*)(vb + (size_t)row * CDIM) + c2 * 16);
        }
    }
    CP_COMMIT();

    uint32_t qa[2][4];
    float o[16][4];
#pragma unroll
    for (int nb = 0; nb < 16; nb++)
#pragma unroll
        for (int j = 0; j < 4; j++) o[nb][j] = 0.0f;
    float lsum0 = 0.0f, lsum1 = 0.0f;

    for (int kt = 0; kt < NTILES; kt++) {
        // issue next tile into the other buffer
        if (kt < NTILES - 1) {
            const int k0n = (kt + 1) * TK;
            const uint32_t bo = ((kt + 1) & 1) * BUFSTRIDE;
            int d = tid >> 4, ch = tid & 15;
            CP_ASYNC16(sb + KS_OFF + bo + d * 272 + ch * 16,
                       (const char*)(kb + (size_t)d * NPIX + k0n) + ch * 16);
#pragma unroll
            for (int i = 0; i < 8; i++) {
                int idx = tid + i * 512;
                int row = idx >> 5, c2 = idx & 31;
                CP_ASYNC16(sb + VS_OFF + bo + row * 528 + c2 * 16,
                           (const char*)(vb + (size_t)(k0n + row) * CDIM) + c2 * 16);
            }
            CP_COMMIT();
            CP_WAIT1();
        } else {
            CP_WAIT0();
        }
        __syncthreads();

        if (kt == 0) {
            int r  = wbase + (lane & 7) + ((lane >> 3) & 1) * 8;
            int cb = (lane >> 4) * 16;
            ldsm4(qa[0], sb + QS_OFF + r * 80 + cb);
            ldsm4(qa[1], sb + QS_OFF + r * 80 + 32 + cb);
        }

        const uint32_t bo = (kt & 1) * BUFSTRIDE;
        const uint32_t kaddr = sb + KS_OFF + bo + lane * 272;
        const uint32_t vbase = sb + VS_OFF + bo + (lane & 15) * 528 + (lane >> 4) * 16
                               + (uint32_t)chalf * 256u;

        // ---- GEMM1 + softmax (duplicated across chalf pair) ----
        uint32_t P[8][4];
#pragma unroll
        for (int jp = 0; jp < 8; jp++) {
#pragma unroll
            for (int jh = 0; jh < 2; jh++) {
                const int j = jp * 2 + jh;
                float c4[4] = {0.0f, 0.0f, 0.0f, 0.0f};
                uint32_t bk4[4];
                ldsm4t(bk4, kaddr + j * 16);
                mma16816(c4, qa[0], bk4);
                mma16816(c4, qa[1], bk4 + 2);
                float e0 = ex2f(c4[0]), e1 = ex2f(c4[1]);
                float e2 = ex2f(c4[2]), e3 = ex2f(c4[3]);
                lsum0 += e0 + e1;
                lsum1 += e2 + e3;
                CVT_BF16X2(P[jp][jh * 2 + 0], e0, e1);
                CVT_BF16X2(P[jp][jh * 2 + 1], e2, e3);
            }
        }

        // ---- GEMM2: O += P * V (this warp's 128 channels) ----
#pragma unroll
        for (int ks = 0; ks < 8; ks++) {
            const uint32_t va = vbase + ks * 8448;     // 16 rows * 528B
#pragma unroll
            for (int jp2 = 0; jp2 < 8; jp2++) {
                uint32_t bv4[4];
                ldsm4t(bv4, va + jp2 * 32);
                mma16816(o[2 * jp2],     P[ks], bv4);
                mma16816(o[2 * jp2 + 1], P[ks], bv4 + 2);
            }
        }
        __syncthreads();
    }

    // ---- row sums -> scale ----
    lsum0 += __shfl_xor_sync(0xffffffffu, lsum0, 1);
    lsum0 += __shfl_xor_sync(0xffffffffu, lsum0, 2);
    lsum1 += __shfl_xor_sync(0xffffffffu, lsum1, 1);
    lsum1 += __shfl_xor_sync(0xffffffffu, lsum1, 2);
    const float gam = gamma[0];
    const float scl0 = gam / lsum0;
    const float scl1 = gam / lsum1;

    // ---- write scaled O to OutS (bf16, 516B row stride) ----
    {
        const uint32_t rbase = sb + OUTS_OFF + (uint32_t)(wbase + qg) * 516u;
#pragma unroll
        for (int jp2 = 0; jp2 < 8; jp2++) {
#pragma unroll
            for (int s = 0; s < 2; s++) {
                const int nb = 2 * jp2 + s;
                const uint32_t cbyte = (uint32_t)(chalf * 128 + jp2 * 16 + s * 8 + 2 * qt) * 2u;
                uint32_t p0, p1;
                CVT_BF16X2(p0, o[nb][0] * scl0, o[nb][1] * scl0);
                CVT_BF16X2(p1, o[nb][2] * scl1, o[nb][3] * scl1);
                STS32(rbase + cbyte, p0);
                STS32(rbase + 8u * 516u + cbyte, p1);
            }
        }
    }
    __syncthreads();

    // ---- residual + LayerNorm: 512 threads = 256 channels x 2 pixel halves ----
    const int c  = tid & 255;
    const int ph = tid >> 8;
    const int q0 = ph * 64;
    const float lw = ln_w[c], lb = ln_b[c];
    float* wsum = reinterpret_cast<float*>(dsm + WS_OFF);
    float* wsq  = reinterpret_cast<float*>(dsm + WQ_OFF);
    float* mst  = reinterpret_cast<float*>(dsm + MST_OFF);
    float* lstd = reinterpret_cast<float*>(dsm + LSTD_OFF);
    const __nv_bfloat16* outs = reinterpret_cast<const __nv_bfloat16*>(dsm + OUTS_OFF);

    float Oc[64];
    const float* xrow = x + ((size_t)b * CDIM + c) * NPIX + n0 + q0;
#pragma unroll
    for (int j4 = 0; j4 < 16; j4++) {
        float4 xv = reinterpret_cast<const float4*>(xrow)[j4];
        float o0 = __bfloat162float(outs[(size_t)(q0 + 4 * j4 + 0) * 258 + c]);
        float o1 = __bfloat162float(outs[(size_t)(q0 + 4 * j4 + 1) * 258 + c]);
        float o2 = __bfloat162float(outs[(size_t)(q0 + 4 * j4 + 2) * 258 + c]);
        float o3 = __bfloat162float(outs[(size_t)(q0 + 4 * j4 + 3) * 258 + c]);
        Oc[4 * j4 + 0] = o0 + xv.x;
        Oc[4 * j4 + 1] = o1 + xv.y;
        Oc[4 * j4 + 2] = o2 + xv.z;
        Oc[4 * j4 + 3] = o3 + xv.w;
    }
#pragma unroll
    for (int q = 0; q < 64; q++) {
        float v = Oc[q];
        float s = v, s2 = v * v;
#pragma unroll
        for (int off = 16; off; off >>= 1) {
            s  += __shfl_xor_sync(0xffffffffu, s,  off);
            s2 += __shfl_xor_sync(0xffffffffu, s2, off);
        }
        if (lane == 0) { wsum[(q0 + q) * 8 + (warp & 7)] = s; wsq[(q0 + q) * 8 + (warp & 7)] = s2; }
    }
    __syncthreads();
    if (tid < 128) {
        float s = 0.0f, s2 = 0.0f;
#pragma unroll
        for (int w = 0; w < 8; w++) { s += wsum[tid * 8 + w]; s2 += wsq[tid * 8 + w]; }
        float mu  = s * (1.0f / CDIM);
        float var = s2 * (1.0f / CDIM) - mu * mu;
        mst[tid]  = mu;
        lstd[tid] = rsqrtf(var + LN_EPS);
    }
    __syncthreads();
    float* orow = out + ((size_t)b * CDIM + c) * NPIX + n0 + q0;
#pragma unroll
    for (int j4 = 0; j4 < 16; j4++) {
        float4 y;
        y.x = fmaf((Oc[4*j4 + 0] - mst[q0 + 4*j4 + 0]) * lstd[q0 + 4*j4 + 0], lw, lb);
        y.y = fmaf((Oc[4*j4 + 1] - mst[q0 + 4*j4 + 1]) * lstd[q0 + 4*j4 + 1], lw, lb);
        y.z = fmaf((Oc[4*j4 + 2] - mst[q0 + 4*j4 + 2]) * lstd[q0 + 4*j4 + 2], lw, lb);
        y.w = fmaf((Oc[4*j4 + 3] - mst[q0 + 4*j4 + 3]) * lstd[q0 + 4*j4 + 3], lw, lb);
        reinterpret_cast<float4*>(orow)[j4] = y;
    }
}

// ---------------------------------------------------------------------------
extern "C" void kernel_launch(void* const* d_in, const int* in_sizes, int n_in,
                              void* d_out, int out_size)
{
    const float* x     = (const float*)d_in[0];
    const float* wq    = (const float*)d_in[1];
    const float* bq    = (const float*)d_in[2];
    const float* wk    = (const float*)d_in[3];
    const float* bk    = (const float*)d_in[4];
    const float* wv    = (const float*)d_in[5];
    const float* bv    = (const float*)d_in[6];
    const float* gamma = (const float*)d_in[7];
    const float* ln_w  = (const float*)d_in[8];
    const float* ln_b  = (const float*)d_in[9];
    float* out = (float*)d_out;

    cudaFuncSetAttribute(attn_kernel, cudaFuncAttributeMaxDynamicSharedMemorySize, SMEM_DYN);

    qkv_kernel<<<dim3(NPIX / 128, 5, BATCH), 256>>>(x, wq, bq, wk, bk, wv, bv);
    attn_kernel<<<dim3(NPIX / MQ, BATCH), 512, SMEM_DYN>>>(x, gamma, ln_w, ln_b, out);
}